// round 1
// baseline (speedup 1.0000x reference)
#include <cuda_runtime.h>
#include <cstdint>
#include <math.h>

#define BV      4
#define NTOK    16384
#define DIMM    512
#define HEADS   8
#define DH      64
#define SEGLEN  64
#define PMT     4

// ---------------- scratch (device globals; no allocation) ----------------
__device__ float g_rms[BV * NTOK];                    // per-row rsqrt(mean(x^2)+eps)
__device__ float g_rope[NTOK * 32 * 2];               // [n][freq][{cos,sin}]
__device__ float g_q[(size_t)BV * HEADS * NTOK * DH]; // (b,h,n,d) roped q
__device__ float g_k[(size_t)BV * HEADS * NTOK * DH]; // (b,h,n,d) roped k
__device__ float g_vfb[(size_t)BV * HEADS * NTOK * DH]; // fallback v if out buffer is small
__device__ float g_att[(size_t)BV * NTOK * DIMM];     // (b,n, h*dh) attention output

// ---------------- K0: rope table ----------------
__global__ void rope_table_kernel() {
    int idx = blockIdx.x * blockDim.x + threadIdx.x;
    if (idx >= NTOK * 32) return;
    int n = idx >> 5, i = idx & 31;
    double p = pow(10000.0, (double)i / 32.0);
    float inv = 1.0f / (float)p;                 // match f32(1/ f32(pow))
    float th = (float)n * inv;                   // match reference f32 angle rounding
    float s, c;
    sincosf(th, &s, &c);
    g_rope[idx * 2 + 0] = c;
    g_rope[idx * 2 + 1] = s;
}

// ---------------- K1: RMS scale per row ----------------
__global__ __launch_bounds__(128) void rms_kernel(const float* __restrict__ seq) {
    int row = blockIdx.x;
    int t = threadIdx.x;                         // 128 threads, 512 floats = 128 float4
    const float4* p = (const float4*)(seq + (size_t)row * DIMM);
    float4 v = p[t];
    float ss = v.x * v.x + v.y * v.y + v.z * v.z + v.w * v.w;
#pragma unroll
    for (int o = 16; o; o >>= 1) ss += __shfl_xor_sync(0xffffffffu, ss, o);
    __shared__ float wsum[4];
    if ((t & 31) == 0) wsum[t >> 5] = ss;
    __syncthreads();
    if (t == 0) {
        float tot = wsum[0] + wsum[1] + wsum[2] + wsum[3];
        g_rms[row] = rsqrtf(tot * (1.0f / DIMM) + 1.1920929e-7f);
    }
}

// ---------------- tf32 helper ----------------
__device__ __forceinline__ uint32_t f2tf(float x) {
    uint32_t r;
    asm("cvt.rna.tf32.f32 %0, %1;" : "=r"(r) : "f"(x));
    return r;
}

// ---------------- K2: QKV GEMM (tf32 mma) + RoPE epilogue ----------------
// Grid: (24, 1024). Block tile 64x64, K=512 loop in steps of 16. 128 threads, 4 warps (2x2), warp tile 32x32.
__global__ __launch_bounds__(128) void qkv_kernel(
    const float* __restrict__ seq, const float* __restrict__ normw,
    const float* __restrict__ Wq, const float* __restrict__ Wkv,
    float* __restrict__ vout_opt) {
    __shared__ float As[64][20];   // row stride 80B (16B aligned), conflict-free frag loads
    __shared__ float Bs[16][72];   // row stride 288B

    float* vout = vout_opt ? vout_opt : g_vfb;

    int cb = blockIdx.x, rb = blockIdx.y;
    int r0 = rb * 64, c0 = cb * 64;
    int b = r0 >> 14, n0 = r0 & 16383;
    int sec = c0 >> 9;                 // 0=q, 1=k, 2=v
    int srcb = sec ? (b ^ 2) : b;      // batch-half swap for kv
    const float* Ap = seq + ((size_t)srcb * NTOK + n0) * DIMM;
    const float* rmsp = g_rms + srcb * NTOK + n0;
    const float* Wp; int ldw, wc0;
    if (sec == 0) { Wp = Wq; ldw = DIMM; wc0 = c0; }
    else          { Wp = Wkv; ldw = 1024; wc0 = c0 - 512; }

    int t = threadIdx.x;
    int warp = t >> 5, lane = t & 31;
    int wm = warp >> 1, wn = warp & 1;
    int g = lane >> 2, t4 = lane & 3;

    float acc[2][4][4];
#pragma unroll
    for (int i = 0; i < 2; i++)
#pragma unroll
        for (int j = 0; j < 4; j++)
#pragma unroll
            for (int k = 0; k < 4; k++) acc[i][j][k] = 0.f;

    for (int kt = 0; kt < 32; kt++) {
        int kbase = kt * 16;
        // A tile 64x16 (scaled by rms * gamma, rounded to tf32)
#pragma unroll
        for (int u = 0; u < 2; u++) {
            int idx = t * 2 + u;
            int row = idx >> 2, kq = idx & 3;
            float4 v4 = *(const float4*)(Ap + (size_t)row * DIMM + kbase + kq * 4);
            float rs = rmsp[row];
            int kg = kbase + kq * 4;
            float4 o4;
            o4.x = __uint_as_float(f2tf(v4.x * rs * normw[kg + 0]));
            o4.y = __uint_as_float(f2tf(v4.y * rs * normw[kg + 1]));
            o4.z = __uint_as_float(f2tf(v4.z * rs * normw[kg + 2]));
            o4.w = __uint_as_float(f2tf(v4.w * rs * normw[kg + 3]));
            *(float4*)&As[row][kq * 4] = o4;
        }
        // B tile 16x64
#pragma unroll
        for (int u = 0; u < 2; u++) {
            int idx = t * 2 + u;
            int row = idx >> 4, cq = idx & 15;
            float4 v4 = *(const float4*)(Wp + (size_t)(kbase + row) * ldw + wc0 + cq * 4);
            float4 o4;
            o4.x = __uint_as_float(f2tf(v4.x));
            o4.y = __uint_as_float(f2tf(v4.y));
            o4.z = __uint_as_float(f2tf(v4.z));
            o4.w = __uint_as_float(f2tf(v4.w));
            *(float4*)&Bs[row][cq * 4] = o4;
        }
        __syncthreads();
#pragma unroll
        for (int kk = 0; kk < 16; kk += 8) {
            uint32_t af[2][4], bf[4][2];
#pragma unroll
            for (int mt = 0; mt < 2; mt++) {
                int mr = wm * 32 + mt * 16;
                af[mt][0] = __float_as_uint(As[mr + g][kk + t4]);
                af[mt][1] = __float_as_uint(As[mr + g + 8][kk + t4]);
                af[mt][2] = __float_as_uint(As[mr + g][kk + t4 + 4]);
                af[mt][3] = __float_as_uint(As[mr + g + 8][kk + t4 + 4]);
            }
#pragma unroll
            for (int nt = 0; nt < 4; nt++) {
                int nc = wn * 32 + nt * 8;
                bf[nt][0] = __float_as_uint(Bs[kk + t4][nc + g]);
                bf[nt][1] = __float_as_uint(Bs[kk + t4 + 4][nc + g]);
            }
#pragma unroll
            for (int mt = 0; mt < 2; mt++)
#pragma unroll
                for (int nt = 0; nt < 4; nt++) {
                    asm volatile(
                        "mma.sync.aligned.m16n8k8.row.col.f32.tf32.tf32.f32 "
                        "{%0,%1,%2,%3},{%4,%5,%6,%7},{%8,%9},{%0,%1,%2,%3};"
                        : "+f"(acc[mt][nt][0]), "+f"(acc[mt][nt][1]),
                          "+f"(acc[mt][nt][2]), "+f"(acc[mt][nt][3])
                        : "r"(af[mt][0]), "r"(af[mt][1]), "r"(af[mt][2]), "r"(af[mt][3]),
                          "r"(bf[nt][0]), "r"(bf[nt][1]));
                }
        }
        __syncthreads();
    }

    // epilogue: rope q/k, write to (b,h,n,d); v raw to out slot
#pragma unroll
    for (int mt = 0; mt < 2; mt++)
#pragma unroll
        for (int nt = 0; nt < 4; nt++)
#pragma unroll
            for (int half = 0; half < 2; half++) {
                int rl = wm * 32 + mt * 16 + g + half * 8;
                int r = r0 + rl;
                int n = r & 16383;
                int c = c0 + wn * 32 + nt * 8 + t4 * 2;
                float e = acc[mt][nt][half * 2 + 0];
                float o = acc[mt][nt][half * 2 + 1];
                if (sec < 2) {
                    int cc = c - sec * 512;
                    int h = cc >> 6, d = cc & 63;
                    int fi = d >> 1;
                    float cs = g_rope[((size_t)n * 32 + fi) * 2 + 0];
                    float sn = g_rope[((size_t)n * 32 + fi) * 2 + 1];
                    float re = e * cs - o * sn;
                    float ro = o * cs + e * sn;
                    float* dst = (sec == 0 ? g_q : g_k) +
                                 (((size_t)(b * HEADS + h) * NTOK + n) * DH + d);
                    *(float2*)dst = make_float2(re, ro);
                } else {
                    int cc = c - 1024;
                    int h = cc >> 6, d = cc & 63;
                    *(float2*)(vout + (((size_t)(b * HEADS + h) * NTOK + n) * DH + d)) =
                        make_float2(e, o);
                }
            }
}

// ---------------- K3: windowed attention, one CTA per (window, head) ----------------
__global__ __launch_bounds__(256) void attn_kernel(const float* __restrict__ tm,
                                                   const float* __restrict__ vsrc_opt) {
    extern __shared__ float sm[];
    float* qs = sm;                 // 64 x 65
    float* ks = qs + 64 * 65;       // 68 x 65
    float* vs = ks + 68 * 65;       // 68 x 65
    float* Ss = vs + 68 * 65;       // 64 x 69

    const float* vsrc = vsrc_opt ? vsrc_opt : g_vfb;

    int wh = blockIdx.x;
    int h = wh & 7, win = wh >> 3;
    int b = win >> 8, wi = win & 255;
    int n0 = wi * SEGLEN;
    int t = threadIdx.x;
    size_t base = ((size_t)(b * HEADS + h) * NTOK + n0) * DH;

    for (int idx = t; idx < 64 * 64; idx += 256) {
        int i = idx >> 6, d = idx & 63;
        qs[i * 65 + d] = g_q[base + idx];
    }
    for (int idx = t; idx < 68 * 64; idx += 256) {
        int j = idx >> 6, d = idx & 63;
        float kk, vv;
        if (j < PMT) {
            kk = tm[h * (PMT * DH) + j * DH + d];                 // task_memory[0]
            vv = tm[HEADS * PMT * DH + h * (PMT * DH) + j * DH + d]; // task_memory[1]
        } else {
            kk = g_k[base + (size_t)(j - PMT) * DH + d];
            vv = vsrc[base + (size_t)(j - PMT) * DH + d];
        }
        ks[j * 65 + d] = kk;
        vs[j * 65 + d] = vv;
    }
    __syncthreads();

    int qi = t & 63, jb = t >> 6;   // 4 j-blocks of 17 keys
#pragma unroll 1
    for (int jj = 0; jj < 17; jj++) {
        int j = jb * 17 + jj;
        float a = 0.f;
#pragma unroll
        for (int d = 0; d < 64; d++) a += qs[qi * 65 + d] * ks[j * 65 + d];
        Ss[qi * 69 + j] = a * 0.125f;
    }
    __syncthreads();

    if (t < 64) {
        float m = -1e30f;
#pragma unroll 1
        for (int j = 0; j < 68; j++) m = fmaxf(m, Ss[t * 69 + j]);
        float s = 0.f;
#pragma unroll 1
        for (int j = 0; j < 68; j++) { float e = expf(Ss[t * 69 + j] - m); Ss[t * 69 + j] = e; s += e; }
        float inv = 1.0f / s;
#pragma unroll 1
        for (int j = 0; j < 68; j++) Ss[t * 69 + j] *= inv;
    }
    __syncthreads();

    int db = t >> 6;                // d block: d = db*16 + dd
    float acc[16];
#pragma unroll
    for (int i = 0; i < 16; i++) acc[i] = 0.f;
#pragma unroll 1
    for (int j = 0; j < 68; j++) {
        float p = Ss[qi * 69 + j];
#pragma unroll
        for (int dd = 0; dd < 16; dd++) acc[dd] += p * vs[j * 65 + db * 16 + dd];
    }
    float* op = g_att + ((size_t)(b * NTOK + n0 + qi)) * DIMM + h * DH + db * 16;
#pragma unroll
    for (int dd = 0; dd < 16; dd += 4)
        *(float4*)(op + dd) = make_float4(acc[dd], acc[dd + 1], acc[dd + 2], acc[dd + 3]);
}

// ---------------- K4: output GEMM (g_att @ Wo) -> d_out ----------------
__global__ __launch_bounds__(128) void outproj_kernel(const float* __restrict__ Wo,
                                                      float* __restrict__ out) {
    __shared__ float As[64][20];
    __shared__ float Bs[16][72];

    int cb = blockIdx.x, rb = blockIdx.y;
    int r0 = rb * 64, c0 = cb * 64;
    const float* Ap = g_att + (size_t)r0 * DIMM;

    int t = threadIdx.x;
    int warp = t >> 5, lane = t & 31;
    int wm = warp >> 1, wn = warp & 1;
    int g = lane >> 2, t4 = lane & 3;

    float acc[2][4][4];
#pragma unroll
    for (int i = 0; i < 2; i++)
#pragma unroll
        for (int j = 0; j < 4; j++)
#pragma unroll
            for (int k = 0; k < 4; k++) acc[i][j][k] = 0.f;

    for (int kt = 0; kt < 32; kt++) {
        int kbase = kt * 16;
#pragma unroll
        for (int u = 0; u < 2; u++) {
            int idx = t * 2 + u;
            int row = idx >> 2, kq = idx & 3;
            float4 v4 = *(const float4*)(Ap + (size_t)row * DIMM + kbase + kq * 4);
            float4 o4;
            o4.x = __uint_as_float(f2tf(v4.x));
            o4.y = __uint_as_float(f2tf(v4.y));
            o4.z = __uint_as_float(f2tf(v4.z));
            o4.w = __uint_as_float(f2tf(v4.w));
            *(float4*)&As[row][kq * 4] = o4;
        }
#pragma unroll
        for (int u = 0; u < 2; u++) {
            int idx = t * 2 + u;
            int row = idx >> 4, cq = idx & 15;
            float4 v4 = *(const float4*)(Wo + (size_t)(kbase + row) * DIMM + c0 + cq * 4);
            float4 o4;
            o4.x = __uint_as_float(f2tf(v4.x));
            o4.y = __uint_as_float(f2tf(v4.y));
            o4.z = __uint_as_float(f2tf(v4.z));
            o4.w = __uint_as_float(f2tf(v4.w));
            *(float4*)&Bs[row][cq * 4] = o4;
        }
        __syncthreads();
#pragma unroll
        for (int kk = 0; kk < 16; kk += 8) {
            uint32_t af[2][4], bf[4][2];
#pragma unroll
            for (int mt = 0; mt < 2; mt++) {
                int mr = wm * 32 + mt * 16;
                af[mt][0] = __float_as_uint(As[mr + g][kk + t4]);
                af[mt][1] = __float_as_uint(As[mr + g + 8][kk + t4]);
                af[mt][2] = __float_as_uint(As[mr + g][kk + t4 + 4]);
                af[mt][3] = __float_as_uint(As[mr + g + 8][kk + t4 + 4]);
            }
#pragma unroll
            for (int nt = 0; nt < 4; nt++) {
                int nc = wn * 32 + nt * 8;
                bf[nt][0] = __float_as_uint(Bs[kk + t4][nc + g]);
                bf[nt][1] = __float_as_uint(Bs[kk + t4 + 4][nc + g]);
            }
#pragma unroll
            for (int mt = 0; mt < 2; mt++)
#pragma unroll
                for (int nt = 0; nt < 4; nt++) {
                    asm volatile(
                        "mma.sync.aligned.m16n8k8.row.col.f32.tf32.tf32.f32 "
                        "{%0,%1,%2,%3},{%4,%5,%6,%7},{%8,%9},{%0,%1,%2,%3};"
                        : "+f"(acc[mt][nt][0]), "+f"(acc[mt][nt][1]),
                          "+f"(acc[mt][nt][2]), "+f"(acc[mt][nt][3])
                        : "r"(af[mt][0]), "r"(af[mt][1]), "r"(af[mt][2]), "r"(af[mt][3]),
                          "r"(bf[nt][0]), "r"(bf[nt][1]));
                }
        }
        __syncthreads();
    }

#pragma unroll
    for (int mt = 0; mt < 2; mt++)
#pragma unroll
        for (int nt = 0; nt < 4; nt++)
#pragma unroll
            for (int half = 0; half < 2; half++) {
                int r = r0 + wm * 32 + mt * 16 + g + half * 8;
                int c = c0 + wn * 32 + nt * 8 + t4 * 2;
                *(float2*)(out + (size_t)r * DIMM + c) =
                    make_float2(acc[mt][nt][half * 2 + 0], acc[mt][nt][half * 2 + 1]);
            }
}

// ---------------- launch ----------------
extern "C" void kernel_launch(void* const* d_in, const int* in_sizes, int n_in,
                              void* d_out, int out_size) {
    const float *seq = 0, *normw = 0, *Wq = 0, *Wkv = 0, *Wo = 0, *tm = 0;
    for (int i = 0; i < n_in; i++) {
        int s = in_sizes[i];
        const float* p = (const float*)d_in[i];
        if (s == 33554432) seq = p;
        else if (s == 512) normw = p;
        else if (s == 524288) Wkv = p;
        else if (s == 4096) tm = p;
        else if (s == 262144) { if (!Wq) Wq = p; else Wo = p; }
    }
    float* out = (float*)d_out;
    float* vout = (out_size >= 67108864) ? (out + 33554432) : nullptr;

    rope_table_kernel<<<2048, 256>>>();
    rms_kernel<<<BV * NTOK, 128>>>(seq);

    dim3 g2(24, 1024);
    qkv_kernel<<<g2, 128>>>(seq, normw, Wq, Wkv, vout);

    const int SMEM_ATTN = (64 * 65 + 68 * 65 + 68 * 65 + 64 * 69) * 4;  // 69664 B
    cudaFuncSetAttribute(attn_kernel, cudaFuncAttributeMaxDynamicSharedMemorySize, SMEM_ATTN);
    attn_kernel<<<BV * 256 * HEADS, 256, SMEM_ATTN>>>(tm, vout);

    dim3 g4(8, 1024);
    outproj_kernel<<<g4, 128>>>(Wo, out);
}

// round 2
// speedup vs baseline: 1.6590x; 1.6590x over previous
#include <cuda_runtime.h>
#include <cstdint>
#include <math.h>

#define BV      4
#define NTOK    16384
#define DIMM    512
#define HEADS   8
#define DH      64
#define SEGLEN  64
#define PMT     4

// ---------------- scratch (device globals; no allocation) ----------------
__device__ float g_rms[BV * NTOK];                     // per-row rsqrt(mean(x^2)+eps)
__device__ float g_rope[NTOK * 32 * 2];                // [n][freq][{cos,sin}]
__device__ float g_xt[(size_t)BV * NTOK * DIMM];       // tf32-rounded x (raw, unscaled)
__device__ float g_wqkv[DIMM * 1536];                  // tf32( gamma_k * [Wq | Wkv] )
__device__ float g_wo[DIMM * DIMM];                    // tf32(Wo)
__device__ float g_q[(size_t)BV * HEADS * NTOK * DH];  // (b,h,n,d) roped q
__device__ float g_k[(size_t)BV * HEADS * NTOK * DH];  // (b,h,n,d) roped k
__device__ float g_vfb[(size_t)BV * HEADS * NTOK * DH];// fallback v
__device__ float g_att[(size_t)BV * NTOK * DIMM];      // (b,n, h*dh) attention output (tf32-rounded)

// ---------------- tf32 helper ----------------
__device__ __forceinline__ uint32_t f2tf(float x) {
    uint32_t r;
    asm("cvt.rna.tf32.f32 %0, %1;" : "=r"(r) : "f"(x));
    return r;
}
__device__ __forceinline__ float tfv(float x) { return __uint_as_float(f2tf(x)); }

// ---------------- cp.async helpers ----------------
__device__ __forceinline__ void cp16(float* smem, const float* g) {
    uint32_t s = (uint32_t)__cvta_generic_to_shared(smem);
    asm volatile("cp.async.cg.shared.global [%0], [%1], 16;\n" ::"r"(s), "l"(g));
}
__device__ __forceinline__ void cp_commit() { asm volatile("cp.async.commit_group;\n"); }
__device__ __forceinline__ void cp_wait1() { asm volatile("cp.async.wait_group 1;\n"); }
__device__ __forceinline__ void cp_wait0() { asm volatile("cp.async.wait_group 0;\n"); }

// ---------------- K0: rope table ----------------
__global__ void rope_table_kernel() {
    int idx = blockIdx.x * blockDim.x + threadIdx.x;
    if (idx >= NTOK * 32) return;
    int n = idx >> 5, i = idx & 31;
    double p = pow(10000.0, (double)i / 32.0);
    float inv = 1.0f / (float)p;
    float th = (float)n * inv;
    float s, c;
    sincosf(th, &s, &c);
    g_rope[idx * 2 + 0] = c;
    g_rope[idx * 2 + 1] = s;
}

// ---------------- prep: weights -> tf32 (gamma folded into qkv weights) ----------------
__global__ void prep_wqkv_kernel(const float* __restrict__ normw,
                                 const float* __restrict__ Wq,
                                 const float* __restrict__ Wkv) {
    int idx = blockIdx.x * blockDim.x + threadIdx.x;
    if (idx >= DIMM * 1536) return;
    int k = idx / 1536, c = idx - k * 1536;
    float w = (c < 512) ? Wq[k * 512 + c] : Wkv[k * 1024 + (c - 512)];
    g_wqkv[idx] = tfv(normw[k] * w);
}
__global__ void prep_wo_kernel(const float* __restrict__ Wo) {
    int idx = blockIdx.x * blockDim.x + threadIdx.x;
    if (idx >= DIMM * DIMM) return;
    g_wo[idx] = tfv(Wo[idx]);
}

// ---------------- K1: RMS per row + tf32 copy of x ----------------
__global__ __launch_bounds__(128) void rms_kernel(const float* __restrict__ seq) {
    int row = blockIdx.x;
    int t = threadIdx.x;
    const float4* p = (const float4*)(seq + (size_t)row * DIMM);
    float4 v = p[t];
    float ss = v.x * v.x + v.y * v.y + v.z * v.z + v.w * v.w;
#pragma unroll
    for (int o = 16; o; o >>= 1) ss += __shfl_xor_sync(0xffffffffu, ss, o);
    __shared__ float wsum[4];
    if ((t & 31) == 0) wsum[t >> 5] = ss;
    __syncthreads();
    if (t == 0) {
        float tot = wsum[0] + wsum[1] + wsum[2] + wsum[3];
        g_rms[row] = rsqrtf(tot * (1.0f / DIMM) + 1.1920929e-7f);
    }
    float4 o4 = make_float4(tfv(v.x), tfv(v.y), tfv(v.z), tfv(v.w));
    *(float4*)(g_xt + (size_t)row * DIMM + t * 4) = o4;
}

// ================= GEMM core (tf32 mma, double-buffered cp.async) =================
// Tile: BM=128, BN=64, BK=32. 256 threads, 8 warps (4x2), warp tile 32x32.
#define ASTR 36
#define BSTR 68
#define A_STG (128 * ASTR)
#define B_STG (32 * BSTR)
#define GEMM_SMEM ((A_STG + B_STG) * 2 * 4)

__device__ __forceinline__ void gemm_loadA(float* sA, const float* Ap, int kbase, int t) {
#pragma unroll
    for (int i = 0; i < 4; i++) {
        int c = t + i * 256;
        int row = c >> 3, seg = c & 7;
        cp16(&sA[row * ASTR + seg * 4], Ap + (size_t)row * DIMM + kbase + seg * 4);
    }
}
__device__ __forceinline__ void gemm_loadB(float* sB, const float* Bp, int ldb, int kbase, int t) {
#pragma unroll
    for (int i = 0; i < 2; i++) {
        int c = t + i * 256;
        int row = c >> 4, seg = c & 15;
        cp16(&sB[row * BSTR + seg * 4], Bp + (size_t)(kbase + row) * ldb + seg * 4);
    }
}

__device__ __forceinline__ void gemm_compute(const float* sA, const float* sB,
                                             float acc[2][4][4],
                                             int wm, int wn, int g, int t4) {
#pragma unroll
    for (int kk = 0; kk < 32; kk += 8) {
        uint32_t af[2][4], bf[4][2];
#pragma unroll
        for (int mt = 0; mt < 2; mt++) {
            int mr = wm * 32 + mt * 16;
            af[mt][0] = __float_as_uint(sA[(mr + g) * ASTR + kk + t4]);
            af[mt][1] = __float_as_uint(sA[(mr + g + 8) * ASTR + kk + t4]);
            af[mt][2] = __float_as_uint(sA[(mr + g) * ASTR + kk + t4 + 4]);
            af[mt][3] = __float_as_uint(sA[(mr + g + 8) * ASTR + kk + t4 + 4]);
        }
#pragma unroll
        for (int nt = 0; nt < 4; nt++) {
            int nc = wn * 32 + nt * 8;
            bf[nt][0] = __float_as_uint(sB[(kk + t4) * BSTR + nc + g]);
            bf[nt][1] = __float_as_uint(sB[(kk + t4 + 4) * BSTR + nc + g]);
        }
#pragma unroll
        for (int mt = 0; mt < 2; mt++)
#pragma unroll
            for (int nt = 0; nt < 4; nt++) {
                asm volatile(
                    "mma.sync.aligned.m16n8k8.row.col.f32.tf32.tf32.f32 "
                    "{%0,%1,%2,%3},{%4,%5,%6,%7},{%8,%9},{%0,%1,%2,%3};"
                    : "+f"(acc[mt][nt][0]), "+f"(acc[mt][nt][1]),
                      "+f"(acc[mt][nt][2]), "+f"(acc[mt][nt][3])
                    : "r"(af[mt][0]), "r"(af[mt][1]), "r"(af[mt][2]), "r"(af[mt][3]),
                      "r"(bf[nt][0]), "r"(bf[nt][1]));
            }
    }
}

// ---------------- K2: QKV GEMM + RoPE epilogue ----------------
// Grid (24, 512): blockIdx.x = 64-col block over 1536, blockIdx.y = 128-row block over 65536.
__global__ __launch_bounds__(256) void qkv_kernel(float* __restrict__ vout_opt) {
    extern __shared__ float smg[];
    float* sA = smg;                       // 2 stages
    float* sB = smg + 2 * A_STG;

    float* vout = vout_opt ? vout_opt : g_vfb;

    int cb = blockIdx.x, rb = blockIdx.y;
    int r0 = rb * 128, c0 = cb * 64;
    int b = r0 >> 14, n0 = r0 & 16383;
    int sec = c0 >> 9;                     // 0=q, 1=k, 2=v
    int srcb = sec ? (b ^ 2) : b;          // batch-half swap for kv
    const float* Ap = g_xt + ((size_t)srcb * NTOK + n0) * DIMM;
    const float* rmsp = g_rms + srcb * NTOK + n0;
    const float* Bp = g_wqkv + c0;

    int t = threadIdx.x;
    int warp = t >> 5, lane = t & 31;
    int wm = warp >> 1, wn = warp & 1;
    int g = lane >> 2, t4 = lane & 3;

    float acc[2][4][4];
#pragma unroll
    for (int i = 0; i < 2; i++)
#pragma unroll
        for (int j = 0; j < 4; j++)
#pragma unroll
            for (int k = 0; k < 4; k++) acc[i][j][k] = 0.f;

    gemm_loadA(sA, Ap, 0, t);
    gemm_loadB(sB, Bp, 1536, 0, t);
    cp_commit();

#pragma unroll 1
    for (int kt = 0; kt < 16; kt++) {
        if (kt + 1 < 16) {
            gemm_loadA(sA + ((kt + 1) & 1) * A_STG, Ap, (kt + 1) * 32, t);
            gemm_loadB(sB + ((kt + 1) & 1) * B_STG, Bp, 1536, (kt + 1) * 32, t);
            cp_commit();
            cp_wait1();
        } else {
            cp_wait0();
        }
        __syncthreads();
        gemm_compute(sA + (kt & 1) * A_STG, sB + (kt & 1) * B_STG, acc, wm, wn, g, t4);
        __syncthreads();
    }

    // epilogue: scale by rms(row), rope q/k, write v
#pragma unroll
    for (int mt = 0; mt < 2; mt++)
#pragma unroll
        for (int half = 0; half < 2; half++) {
            int rl = wm * 32 + mt * 16 + g + half * 8;
            float rs = rmsp[rl];
            int n = n0 + rl;
#pragma unroll
            for (int nt = 0; nt < 4; nt++) {
                int c = c0 + wn * 32 + nt * 8 + t4 * 2;
                float e = acc[mt][nt][half * 2 + 0] * rs;
                float o = acc[mt][nt][half * 2 + 1] * rs;
                if (sec < 2) {
                    int cc = c - sec * 512;
                    int h = cc >> 6, d = cc & 63;
                    int fi = d >> 1;
                    float cs = g_rope[((size_t)n * 32 + fi) * 2 + 0];
                    float sn = g_rope[((size_t)n * 32 + fi) * 2 + 1];
                    float re = e * cs - o * sn;
                    float ro = o * cs + e * sn;
                    float* dst = (sec == 0 ? g_q : g_k) +
                                 (((size_t)(b * HEADS + h) * NTOK + n) * DH + d);
                    *(float2*)dst = make_float2(re, ro);
                } else {
                    int cc = c - 1024;
                    int h = cc >> 6, d = cc & 63;
                    *(float2*)(vout + (((size_t)(b * HEADS + h) * NTOK + n) * DH + d)) =
                        make_float2(e, o);
                }
            }
        }
}

// ---------------- K4: output GEMM (g_att @ g_wo) -> d_out ----------------
// Grid (8, 512)
__global__ __launch_bounds__(256) void outproj_kernel(float* __restrict__ out) {
    extern __shared__ float smg[];
    float* sA = smg;
    float* sB = smg + 2 * A_STG;

    int cb = blockIdx.x, rb = blockIdx.y;
    int r0 = rb * 128, c0 = cb * 64;
    const float* Ap = g_att + (size_t)r0 * DIMM;
    const float* Bp = g_wo + c0;

    int t = threadIdx.x;
    int warp = t >> 5, lane = t & 31;
    int wm = warp >> 1, wn = warp & 1;
    int g = lane >> 2, t4 = lane & 3;

    float acc[2][4][4];
#pragma unroll
    for (int i = 0; i < 2; i++)
#pragma unroll
        for (int j = 0; j < 4; j++)
#pragma unroll
            for (int k = 0; k < 4; k++) acc[i][j][k] = 0.f;

    gemm_loadA(sA, Ap, 0, t);
    gemm_loadB(sB, Bp, DIMM, 0, t);
    cp_commit();

#pragma unroll 1
    for (int kt = 0; kt < 16; kt++) {
        if (kt + 1 < 16) {
            gemm_loadA(sA + ((kt + 1) & 1) * A_STG, Ap, (kt + 1) * 32, t);
            gemm_loadB(sB + ((kt + 1) & 1) * B_STG, Bp, DIMM, (kt + 1) * 32, t);
            cp_commit();
            cp_wait1();
        } else {
            cp_wait0();
        }
        __syncthreads();
        gemm_compute(sA + (kt & 1) * A_STG, sB + (kt & 1) * B_STG, acc, wm, wn, g, t4);
        __syncthreads();
    }

#pragma unroll
    for (int mt = 0; mt < 2; mt++)
#pragma unroll
        for (int half = 0; half < 2; half++) {
            int r = r0 + wm * 32 + mt * 16 + g + half * 8;
#pragma unroll
            for (int nt = 0; nt < 4; nt++) {
                int c = c0 + wn * 32 + nt * 8 + t4 * 2;
                *(float2*)(out + (size_t)r * DIMM + c) =
                    make_float2(acc[mt][nt][half * 2 + 0], acc[mt][nt][half * 2 + 1]);
            }
        }
}

// ---------------- K3: windowed attention, register-tiled FFMA ----------------
// One CTA per (window, head). 256 threads.
// smem: qs[64][65], ks[80][65] (rows 68..79 zero), Ss[64][80]
#define QSTR 65
#define ATT_SMEM ((64 * QSTR + 80 * QSTR + 64 * 80) * 4)

__global__ __launch_bounds__(256) void attn_kernel(const float* __restrict__ tm,
                                                   const float* __restrict__ vsrc_opt) {
    extern __shared__ float sm[];
    float* qs = sm;                   // 64 x 65
    float* ks = qs + 64 * QSTR;       // 80 x 65
    float* Ss = ks + 80 * QSTR;       // 64 x 80

    const float* vsrc = vsrc_opt ? vsrc_opt : g_vfb;

    int wh = blockIdx.x;
    int h = wh & 7, win = wh >> 3;
    int b = win >> 8, wi = win & 255;
    int n0 = wi * SEGLEN;
    int t = threadIdx.x;
    size_t base = ((size_t)(b * HEADS + h) * NTOK + n0) * DH;

    // load q (64x64) -> qs
#pragma unroll
    for (int i = 0; i < 4; i++) {
        int c = t + i * 256;          // 1024 float4 chunks
        int row = c >> 4, seg = c & 15;
        float4 v4 = *(const float4*)(g_q + base + (size_t)row * DH + seg * 4);
        float* d = &qs[row * QSTR + seg * 4];
        d[0] = v4.x; d[1] = v4.y; d[2] = v4.z; d[3] = v4.w;
    }
    // load k: rows 0..3 = task mem, 4..67 from g_k, 68..79 zero
#pragma unroll
    for (int i = 0; i < 5; i++) {
        int c = t + i * 256;          // 1280 chunks = 80 rows x 16
        int row = c >> 4, seg = c & 15;
        float4 v4;
        if (row < PMT)
            v4 = *(const float4*)(tm + h * (PMT * DH) + row * DH + seg * 4);
        else if (row < 68)
            v4 = *(const float4*)(g_k + base + (size_t)(row - PMT) * DH + seg * 4);
        else
            v4 = make_float4(0.f, 0.f, 0.f, 0.f);
        float* d = &ks[row * QSTR + seg * 4];
        d[0] = v4.x; d[1] = v4.y; d[2] = v4.z; d[3] = v4.w;
    }
    __syncthreads();

    // phase 1: S = Q K^T * 0.125 ; thread tile 4q x 5j
    int tq = t >> 4, tj = t & 15;
    int qi0 = tq * 4, j0 = tj * 5;
    {
        float accS[4][5];
#pragma unroll
        for (int i = 0; i < 4; i++)
#pragma unroll
            for (int j = 0; j < 5; j++) accS[i][j] = 0.f;
#pragma unroll 4
        for (int d = 0; d < 64; d++) {
            float qv[4], kv[5];
#pragma unroll
            for (int i = 0; i < 4; i++) qv[i] = qs[(qi0 + i) * QSTR + d];
#pragma unroll
            for (int j = 0; j < 5; j++) kv[j] = ks[(j0 + j) * QSTR + d];
#pragma unroll
            for (int i = 0; i < 4; i++)
#pragma unroll
                for (int j = 0; j < 5; j++) accS[i][j] += qv[i] * kv[j];
        }
#pragma unroll
        for (int i = 0; i < 4; i++)
#pragma unroll
            for (int j = 0; j < 5; j++)
                if (j0 + j < 68) Ss[(qi0 + i) * 80 + j0 + j] = accS[i][j] * 0.125f;
    }
    __syncthreads();

    // softmax: one thread per query row
    if (t < 64) {
        float m = -1e30f;
#pragma unroll 4
        for (int j = 0; j < 68; j++) m = fmaxf(m, Ss[t * 80 + j]);
        float s = 0.f;
#pragma unroll 4
        for (int j = 0; j < 68; j++) {
            float e = expf(Ss[t * 80 + j] - m);
            Ss[t * 80 + j] = e;
            s += e;
        }
        float inv = 1.0f / s;
#pragma unroll 4
        for (int j = 0; j < 68; j++) Ss[t * 80 + j] *= inv;
    }
    __syncthreads();

    // phase 2: O = P V ; thread tile 4q x 4d ; V read from gmem (L1)
    int td = t & 15, d0 = td * 4;
    float acc[4][4];
#pragma unroll
    for (int i = 0; i < 4; i++)
#pragma unroll
        for (int k = 0; k < 4; k++) acc[i][k] = 0.f;

    const float* tmv = tm + HEADS * PMT * DH + h * (PMT * DH);
#pragma unroll
    for (int j = 0; j < PMT; j++) {
        float4 v4 = *(const float4*)(tmv + j * DH + d0);
        float p[4];
#pragma unroll
        for (int i = 0; i < 4; i++) p[i] = Ss[(qi0 + i) * 80 + j];
#pragma unroll
        for (int i = 0; i < 4; i++) {
            acc[i][0] += p[i] * v4.x; acc[i][1] += p[i] * v4.y;
            acc[i][2] += p[i] * v4.z; acc[i][3] += p[i] * v4.w;
        }
    }
#pragma unroll 4
    for (int j = PMT; j < 68; j++) {
        float4 v4 = *(const float4*)(vsrc + base + (size_t)(j - PMT) * DH + d0);
        float p[4];
#pragma unroll
        for (int i = 0; i < 4; i++) p[i] = Ss[(qi0 + i) * 80 + j];
#pragma unroll
        for (int i = 0; i < 4; i++) {
            acc[i][0] += p[i] * v4.x; acc[i][1] += p[i] * v4.y;
            acc[i][2] += p[i] * v4.z; acc[i][3] += p[i] * v4.w;
        }
    }

    // store tf32-rounded so outproj needs no conversion
#pragma unroll
    for (int i = 0; i < 4; i++) {
        float* op = g_att + ((size_t)(b * NTOK + n0 + qi0 + i)) * DIMM + h * DH + d0;
        *(float4*)op = make_float4(tfv(acc[i][0]), tfv(acc[i][1]),
                                   tfv(acc[i][2]), tfv(acc[i][3]));
    }
}

// ---------------- launch ----------------
extern "C" void kernel_launch(void* const* d_in, const int* in_sizes, int n_in,
                              void* d_out, int out_size) {
    const float *seq = 0, *normw = 0, *Wq = 0, *Wkv = 0, *Wo = 0, *tm = 0;
    for (int i = 0; i < n_in; i++) {
        int s = in_sizes[i];
        const float* p = (const float*)d_in[i];
        if (s == 33554432) seq = p;
        else if (s == 512) normw = p;
        else if (s == 524288) Wkv = p;
        else if (s == 4096) tm = p;
        else if (s == 262144) { if (!Wq) Wq = p; else Wo = p; }
    }
    float* out = (float*)d_out;
    float* vout = (out_size >= 67108864) ? (out + 33554432) : nullptr;

    rope_table_kernel<<<2048, 256>>>();
    prep_wqkv_kernel<<<3072, 256>>>(normw, Wq, Wkv);
    prep_wo_kernel<<<1024, 256>>>(Wo);
    rms_kernel<<<BV * NTOK, 128>>>(seq);

    cudaFuncSetAttribute(qkv_kernel, cudaFuncAttributeMaxDynamicSharedMemorySize, GEMM_SMEM);
    cudaFuncSetAttribute(outproj_kernel, cudaFuncAttributeMaxDynamicSharedMemorySize, GEMM_SMEM);
    cudaFuncSetAttribute(attn_kernel, cudaFuncAttributeMaxDynamicSharedMemorySize, ATT_SMEM);

    dim3 g2(24, 512);
    qkv_kernel<<<g2, 256, GEMM_SMEM>>>(vout);

    attn_kernel<<<BV * 256 * HEADS, 256, ATT_SMEM>>>(tm, vout);

    dim3 g4(8, 512);
    outproj_kernel<<<g4, 256, GEMM_SMEM>>>(out);
}

// round 4
// speedup vs baseline: 1.7901x; 1.0790x over previous
#include <cuda_runtime.h>
#include <cstdint>
#include <math.h>

#define BV      4
#define NTOK    16384
#define DIMM    512
#define HEADS   8
#define DH      64
#define SEGLEN  64
#define PMT     4

// ---------------- scratch (device globals; no allocation) ----------------
__device__ float g_rms[BV * NTOK];                     // per-row rsqrt(mean(x^2)+eps)
__device__ float g_rope[NTOK * 64];                    // [n][fi][{cos,sin}]
__device__ float g_xt[(size_t)BV * NTOK * DIMM];       // tf32-rounded x (raw, unscaled)
__device__ float g_wqkv[DIMM * 1536];                  // tf32( gamma_k * [Wq | Wkv] )
__device__ float g_wo[DIMM * DIMM];                    // tf32(Wo)
__device__ float g_q[(size_t)BV * HEADS * NTOK * DH];  // (b,h,n,d) roped q
__device__ float g_k[(size_t)BV * HEADS * NTOK * DH];  // (b,h,n,d) roped k
__device__ float g_vfb[(size_t)BV * HEADS * NTOK * DH];// fallback v
__device__ float g_att[(size_t)BV * NTOK * DIMM];      // (b,n, h*dh) attention output (tf32-rounded)

// ---------------- tf32 helper ----------------
__device__ __forceinline__ uint32_t f2tf(float x) {
    uint32_t r;
    asm("cvt.rna.tf32.f32 %0, %1;" : "=r"(r) : "f"(x));
    return r;
}
__device__ __forceinline__ float tfv(float x) { return __uint_as_float(f2tf(x)); }

// ---------------- cp.async helpers ----------------
__device__ __forceinline__ void cp16(float* smem, const float* g) {
    uint32_t s = (uint32_t)__cvta_generic_to_shared(smem);
    asm volatile("cp.async.cg.shared.global [%0], [%1], 16;\n" ::"r"(s), "l"(g));
}
__device__ __forceinline__ void cp_commit() { asm volatile("cp.async.commit_group;\n"); }
__device__ __forceinline__ void cp_wait1() { asm volatile("cp.async.wait_group 1;\n"); }
__device__ __forceinline__ void cp_wait0() { asm volatile("cp.async.wait_group 0;\n"); }

// ---------------- K0: rope table ----------------
__global__ void rope_table_kernel() {
    int idx = blockIdx.x * blockDim.x + threadIdx.x;
    if (idx >= NTOK * 32) return;
    int n = idx >> 5, i = idx & 31;
    double p = pow(10000.0, (double)i / 32.0);
    float inv = 1.0f / (float)p;
    float th = (float)n * inv;
    float s, c;
    sincosf(th, &s, &c);
    g_rope[idx * 2 + 0] = c;
    g_rope[idx * 2 + 1] = s;
}

// ---------------- prep: weights -> tf32 (gamma folded into qkv weights) ----------------
__global__ void prep_wqkv_kernel(const float* __restrict__ normw,
                                 const float* __restrict__ Wq,
                                 const float* __restrict__ Wkv) {
    int idx = blockIdx.x * blockDim.x + threadIdx.x;
    if (idx >= DIMM * 1536) return;
    int k = idx / 1536, c = idx - k * 1536;
    float w = (c < 512) ? Wq[k * 512 + c] : Wkv[k * 1024 + (c - 512)];
    g_wqkv[idx] = tfv(normw[k] * w);
}
__global__ void prep_wo_kernel(const float* __restrict__ Wo) {
    int idx = blockIdx.x * blockDim.x + threadIdx.x;
    if (idx >= DIMM * DIMM) return;
    g_wo[idx] = tfv(Wo[idx]);
}

// ---------------- K1: RMS per row + tf32 copy of x ----------------
__global__ __launch_bounds__(128) void rms_kernel(const float* __restrict__ seq) {
    int row = blockIdx.x;
    int t = threadIdx.x;
    const float4* p = (const float4*)(seq + (size_t)row * DIMM);
    float4 v = p[t];
    float ss = v.x * v.x + v.y * v.y + v.z * v.z + v.w * v.w;
#pragma unroll
    for (int o = 16; o; o >>= 1) ss += __shfl_xor_sync(0xffffffffu, ss, o);
    __shared__ float wsum[4];
    if ((t & 31) == 0) wsum[t >> 5] = ss;
    __syncthreads();
    if (t == 0) {
        float tot = wsum[0] + wsum[1] + wsum[2] + wsum[3];
        g_rms[row] = rsqrtf(tot * (1.0f / DIMM) + 1.1920929e-7f);
    }
    float4 o4 = make_float4(tfv(v.x), tfv(v.y), tfv(v.z), tfv(v.w));
    *(float4*)(g_xt + (size_t)row * DIMM + t * 4) = o4;
}

// ================= GEMM core (tf32 mma, double-buffered cp.async) =================
// Tile: BM=128, BN=128, BK=32. 256 threads, 8 warps (2m x 4n), warp tile 64x32.
#define ASTR 36
#define BSTR 132
#define A_STG (128 * ASTR)
#define B_STG (32 * BSTR)
#define GEMM_SMEM ((A_STG + B_STG) * 2 * 4)

__device__ __forceinline__ void gemm_loadA(float* sA, const float* Ap, int kbase, int t) {
#pragma unroll
    for (int i = 0; i < 4; i++) {
        int c = t + i * 256;
        int row = c >> 3, seg = c & 7;
        cp16(&sA[row * ASTR + seg * 4], Ap + (size_t)row * DIMM + kbase + seg * 4);
    }
}
__device__ __forceinline__ void gemm_loadB(float* sB, const float* Bp, int ldb, int kbase, int t) {
#pragma unroll
    for (int i = 0; i < 4; i++) {
        int c = t + i * 256;
        int row = c >> 5, seg = c & 31;
        cp16(&sB[row * BSTR + seg * 4], Bp + (size_t)(kbase + row) * ldb + seg * 4);
    }
}

__device__ __forceinline__ void gemm_compute(const float* sA, const float* sB,
                                             float acc[4][4][4],
                                             int wm, int wn, int g, int t4) {
#pragma unroll
    for (int kk = 0; kk < 32; kk += 8) {
        uint32_t af[4][4], bf[4][2];
#pragma unroll
        for (int mt = 0; mt < 4; mt++) {
            int mr = wm * 64 + mt * 16;
            af[mt][0] = __float_as_uint(sA[(mr + g) * ASTR + kk + t4]);
            af[mt][1] = __float_as_uint(sA[(mr + g + 8) * ASTR + kk + t4]);
            af[mt][2] = __float_as_uint(sA[(mr + g) * ASTR + kk + t4 + 4]);
            af[mt][3] = __float_as_uint(sA[(mr + g + 8) * ASTR + kk + t4 + 4]);
        }
#pragma unroll
        for (int nt = 0; nt < 4; nt++) {
            int nc = wn * 32 + nt * 8;
            bf[nt][0] = __float_as_uint(sB[(kk + t4) * BSTR + nc + g]);
            bf[nt][1] = __float_as_uint(sB[(kk + t4 + 4) * BSTR + nc + g]);
        }
#pragma unroll
        for (int mt = 0; mt < 4; mt++)
#pragma unroll
            for (int nt = 0; nt < 4; nt++) {
                asm volatile(
                    "mma.sync.aligned.m16n8k8.row.col.f32.tf32.tf32.f32 "
                    "{%0,%1,%2,%3},{%4,%5,%6,%7},{%8,%9},{%0,%1,%2,%3};"
                    : "+f"(acc[mt][nt][0]), "+f"(acc[mt][nt][1]),
                      "+f"(acc[mt][nt][2]), "+f"(acc[mt][nt][3])
                    : "r"(af[mt][0]), "r"(af[mt][1]), "r"(af[mt][2]), "r"(af[mt][3]),
                      "r"(bf[nt][0]), "r"(bf[nt][1]));
            }
    }
}

// ---------------- K2: QKV GEMM + RoPE epilogue ----------------
// Grid (12, 512): x = 128-col block over 1536 (x-major order keeps A hot in L2).
__global__ __launch_bounds__(256) void qkv_kernel(float* __restrict__ vout_opt) {
    extern __shared__ float smg[];
    float* sA = smg;
    float* sB = smg + 2 * A_STG;

    float* vout = vout_opt ? vout_opt : g_vfb;

    int cb = blockIdx.x, rb = blockIdx.y;
    int r0 = rb * 128, c0 = cb * 128;
    int b = r0 >> 14, n0 = r0 & 16383;
    int sec = c0 >> 9;                     // 0=q, 1=k, 2=v
    int srcb = sec ? (b ^ 2) : b;          // batch-half swap for kv
    const float* Ap = g_xt + ((size_t)srcb * NTOK + n0) * DIMM;
    const float* rmsp = g_rms + srcb * NTOK + n0;
    const float* Bp = g_wqkv + c0;

    int t = threadIdx.x;
    int warp = t >> 5, lane = t & 31;
    int wm = warp >> 2, wn = warp & 3;
    int g = lane >> 2, t4 = lane & 3;

    float acc[4][4][4];
#pragma unroll
    for (int i = 0; i < 4; i++)
#pragma unroll
        for (int j = 0; j < 4; j++)
#pragma unroll
            for (int k = 0; k < 4; k++) acc[i][j][k] = 0.f;

    gemm_loadA(sA, Ap, 0, t);
    gemm_loadB(sB, Bp, 1536, 0, t);
    cp_commit();

#pragma unroll 1
    for (int kt = 0; kt < 16; kt++) {
        if (kt + 1 < 16) {
            gemm_loadA(sA + ((kt + 1) & 1) * A_STG, Ap, (kt + 1) * 32, t);
            gemm_loadB(sB + ((kt + 1) & 1) * B_STG, Bp, 1536, (kt + 1) * 32, t);
            cp_commit();
            cp_wait1();
        } else {
            cp_wait0();
        }
        __syncthreads();
        gemm_compute(sA + (kt & 1) * A_STG, sB + (kt & 1) * B_STG, acc, wm, wn, g, t4);
        __syncthreads();
    }

    // epilogue: scale by rms(row), rope q/k, write v
#pragma unroll
    for (int mt = 0; mt < 4; mt++)
#pragma unroll
        for (int half = 0; half < 2; half++) {
            int rl = wm * 64 + mt * 16 + g + half * 8;
            float rs = rmsp[rl];
            int n = n0 + rl;
#pragma unroll
            for (int nt = 0; nt < 4; nt++) {
                int c = c0 + wn * 32 + nt * 8 + t4 * 2;
                float e = acc[mt][nt][half * 2 + 0] * rs;
                float o = acc[mt][nt][half * 2 + 1] * rs;
                if (sec < 2) {
                    int cc = c - sec * 512;
                    int h = cc >> 6, d = cc & 63;
                    int fi = d >> 1;
                    float cs = g_rope[((size_t)n * 32 + fi) * 2 + 0];
                    float sn = g_rope[((size_t)n * 32 + fi) * 2 + 1];
                    float re = e * cs - o * sn;
                    float ro = o * cs + e * sn;
                    float* dst = (sec == 0 ? g_q : g_k) +
                                 (((size_t)(b * HEADS + h) * NTOK + n) * DH + d);
                    *(float2*)dst = make_float2(re, ro);
                } else {
                    int cc = c - 1024;
                    int h = cc >> 6, d = cc & 63;
                    *(float2*)(vout + (((size_t)(b * HEADS + h) * NTOK + n) * DH + d)) =
                        make_float2(e, o);
                }
            }
        }
}

// ---------------- K4: output GEMM (g_att @ g_wo) -> d_out ----------------
// Grid (4, 512)
__global__ __launch_bounds__(256) void outproj_kernel(float* __restrict__ out) {
    extern __shared__ float smg[];
    float* sA = smg;
    float* sB = smg + 2 * A_STG;

    int cb = blockIdx.x, rb = blockIdx.y;
    int r0 = rb * 128, c0 = cb * 128;
    const float* Ap = g_att + (size_t)r0 * DIMM;
    const float* Bp = g_wo + c0;

    int t = threadIdx.x;
    int warp = t >> 5, lane = t & 31;
    int wm = warp >> 2, wn = warp & 3;
    int g = lane >> 2, t4 = lane & 3;

    float acc[4][4][4];
#pragma unroll
    for (int i = 0; i < 4; i++)
#pragma unroll
        for (int j = 0; j < 4; j++)
#pragma unroll
            for (int k = 0; k < 4; k++) acc[i][j][k] = 0.f;

    gemm_loadA(sA, Ap, 0, t);
    gemm_loadB(sB, Bp, DIMM, 0, t);
    cp_commit();

#pragma unroll 1
    for (int kt = 0; kt < 16; kt++) {
        if (kt + 1 < 16) {
            gemm_loadA(sA + ((kt + 1) & 1) * A_STG, Ap, (kt + 1) * 32, t);
            gemm_loadB(sB + ((kt + 1) & 1) * B_STG, Bp, DIMM, (kt + 1) * 32, t);
            cp_commit();
            cp_wait1();
        } else {
            cp_wait0();
        }
        __syncthreads();
        gemm_compute(sA + (kt & 1) * A_STG, sB + (kt & 1) * B_STG, acc, wm, wn, g, t4);
        __syncthreads();
    }

#pragma unroll
    for (int mt = 0; mt < 4; mt++)
#pragma unroll
        for (int half = 0; half < 2; half++) {
            int r = r0 + wm * 64 + mt * 16 + g + half * 8;
#pragma unroll
            for (int nt = 0; nt < 4; nt++) {
                int c = c0 + wn * 32 + nt * 8 + t4 * 2;
                *(float2*)(out + (size_t)r * DIMM + c) =
                    make_float2(acc[mt][nt][half * 2 + 0], acc[mt][nt][half * 2 + 1]);
            }
        }
}

// ---------------- K3: windowed attention (register-tiled FFMA) ----------------
#define QSTR 65
#define ATT_SMEM ((64 * QSTR + 80 * QSTR + 64 * 80) * 4)

__global__ __launch_bounds__(256) void attn_kernel(const float* __restrict__ tm,
                                                   const float* __restrict__ vsrc_opt) {
    extern __shared__ float sm[];
    float* qs = sm;
    float* ks = qs + 64 * QSTR;
    float* Ss = ks + 80 * QSTR;

    const float* vsrc = vsrc_opt ? vsrc_opt : g_vfb;

    int wh = blockIdx.x;
    int h = wh & 7, win = wh >> 3;
    int b = win >> 8, wi = win & 255;
    int n0 = wi * SEGLEN;
    int t = threadIdx.x;
    size_t base = ((size_t)(b * HEADS + h) * NTOK + n0) * DH;

#pragma unroll
    for (int i = 0; i < 4; i++) {
        int c = t + i * 256;
        int row = c >> 4, seg = c & 15;
        float4 v4 = *(const float4*)(g_q + base + (size_t)row * DH + seg * 4);
        float* d = &qs[row * QSTR + seg * 4];
        d[0] = v4.x; d[1] = v4.y; d[2] = v4.z; d[3] = v4.w;
    }
#pragma unroll
    for (int i = 0; i < 5; i++) {
        int c = t + i * 256;
        int row = c >> 4, seg = c & 15;
        float4 v4;
        if (row < PMT)
            v4 = *(const float4*)(tm + h * (PMT * DH) + row * DH + seg * 4);
        else if (row < 68)
            v4 = *(const float4*)(g_k + base + (size_t)(row - PMT) * DH + seg * 4);
        else
            v4 = make_float4(0.f, 0.f, 0.f, 0.f);
        float* d = &ks[row * QSTR + seg * 4];
        d[0] = v4.x; d[1] = v4.y; d[2] = v4.z; d[3] = v4.w;
    }
    __syncthreads();

    int tq = t >> 4, tj = t & 15;
    int qi0 = tq * 4, j0 = tj * 5;
    {
        float accS[4][5];
#pragma unroll
        for (int i = 0; i < 4; i++)
#pragma unroll
            for (int j = 0; j < 5; j++) accS[i][j] = 0.f;
#pragma unroll 4
        for (int d = 0; d < 64; d++) {
            float qv[4], kv[5];
#pragma unroll
            for (int i = 0; i < 4; i++) qv[i] = qs[(qi0 + i) * QSTR + d];
#pragma unroll
            for (int j = 0; j < 5; j++) kv[j] = ks[(j0 + j) * QSTR + d];
#pragma unroll
            for (int i = 0; i < 4; i++)
#pragma unroll
                for (int j = 0; j < 5; j++) accS[i][j] += qv[i] * kv[j];
        }
#pragma unroll
        for (int i = 0; i < 4; i++)
#pragma unroll
            for (int j = 0; j < 5; j++)
                if (j0 + j < 68) Ss[(qi0 + i) * 80 + j0 + j] = accS[i][j] * 0.125f;
    }
    __syncthreads();

    if (t < 64) {
        float m = -1e30f;
#pragma unroll 4
        for (int j = 0; j < 68; j++) m = fmaxf(m, Ss[t * 80 + j]);
        float s = 0.f;
#pragma unroll 4
        for (int j = 0; j < 68; j++) {
            float e = expf(Ss[t * 80 + j] - m);
            Ss[t * 80 + j] = e;
            s += e;
        }
        float inv = 1.0f / s;
#pragma unroll 4
        for (int j = 0; j < 68; j++) Ss[t * 80 + j] *= inv;
    }
    __syncthreads();

    int td = t & 15, d0 = td * 4;
    float acc[4][4];
#pragma unroll
    for (int i = 0; i < 4; i++)
#pragma unroll
        for (int k = 0; k < 4; k++) acc[i][k] = 0.f;

    const float* tmv = tm + HEADS * PMT * DH + h * (PMT * DH);
#pragma unroll
    for (int j = 0; j < PMT; j++) {
        float4 v4 = *(const float4*)(tmv + j * DH + d0);
        float p[4];
#pragma unroll
        for (int i = 0; i < 4; i++) p[i] = Ss[(qi0 + i) * 80 + j];
#pragma unroll
        for (int i = 0; i < 4; i++) {
            acc[i][0] += p[i] * v4.x; acc[i][1] += p[i] * v4.y;
            acc[i][2] += p[i] * v4.z; acc[i][3] += p[i] * v4.w;
        }
    }
#pragma unroll 4
    for (int j = PMT; j < 68; j++) {
        float4 v4 = *(const float4*)(vsrc + base + (size_t)(j - PMT) * DH + d0);
        float p[4];
#pragma unroll
        for (int i = 0; i < 4; i++) p[i] = Ss[(qi0 + i) * 80 + j];
#pragma unroll
        for (int i = 0; i < 4; i++) {
            acc[i][0] += p[i] * v4.x; acc[i][1] += p[i] * v4.y;
            acc[i][2] += p[i] * v4.z; acc[i][3] += p[i] * v4.w;
        }
    }

#pragma unroll
    for (int i = 0; i < 4; i++) {
        float* op = g_att + ((size_t)(b * NTOK + n0 + qi0 + i)) * DIMM + h * DH + d0;
        *(float4*)op = make_float4(tfv(acc[i][0]), tfv(acc[i][1]),
                                   tfv(acc[i][2]), tfv(acc[i][3]));
    }
}

// ---------------- launch ----------------
extern "C" void kernel_launch(void* const* d_in, const int* in_sizes, int n_in,
                              void* d_out, int out_size) {
    const float *seq = 0, *normw = 0, *Wq = 0, *Wkv = 0, *Wo = 0, *tm = 0;
    for (int i = 0; i < n_in; i++) {
        int s = in_sizes[i];
        const float* p = (const float*)d_in[i];
        if (s == 33554432) seq = p;
        else if (s == 512) normw = p;
        else if (s == 524288) Wkv = p;
        else if (s == 4096) tm = p;
        else if (s == 262144) { if (!Wq) Wq = p; else Wo = p; }
    }
    float* out = (float*)d_out;
    float* vout = (out_size >= 67108864) ? (out + 33554432) : nullptr;

    rope_table_kernel<<<2048, 256>>>();
    prep_wqkv_kernel<<<3072, 256>>>(normw, Wq, Wkv);
    prep_wo_kernel<<<1024, 256>>>(Wo);
    rms_kernel<<<BV * NTOK, 128>>>(seq);

    cudaFuncSetAttribute(qkv_kernel, cudaFuncAttributeMaxDynamicSharedMemorySize, GEMM_SMEM);
    cudaFuncSetAttribute(outproj_kernel, cudaFuncAttributeMaxDynamicSharedMemorySize, GEMM_SMEM);
    cudaFuncSetAttribute(attn_kernel, cudaFuncAttributeMaxDynamicSharedMemorySize, ATT_SMEM);

    dim3 g2(12, 512);
    qkv_kernel<<<g2, 256, GEMM_SMEM>>>(vout);

    attn_kernel<<<BV * 256 * HEADS, 256, ATT_SMEM>>>(tm, vout);

    dim3 g4(4, 512);
    outproj_kernel<<<g4, 256, GEMM_SMEM>>>(out);
}